// round 2
// baseline (speedup 1.0000x reference)
#include <cuda_runtime.h>
#include <cuda_bf16.h>
#include <cstdint>

#define EPSF 1e-8f
static constexpr int B_  = 8;
static constexpr int N_  = 256;
static constexpr int NF_ = 2048;

// K matrices (bf16) staged in global (L2-resident), per-batch arrival counters.
__device__ __nv_bfloat16 g_K[B_ * N_ * N_];
__device__ int g_cnt[B_];

// ---- shared memory layout (bytes) ----
// [0,131072)        Ks   : bf16[256*256]
// [131072,147456)   part : float[16*256]   (pool reuses first 4KB as srow)
// [147456,153600)   theta,gam,p,u,v,Kv : 6 * float[256]
// [153600,153792)   red  : float[48]
// [153792,153808)   flg  : int[4]
static constexpr int SMEM_B = 153856;

__device__ __forceinline__ void unpack8(uint4 kr, float* f)
{
    float2 f0 = __bfloat1622float2(*reinterpret_cast<__nv_bfloat162*>(&kr.x));
    float2 f1 = __bfloat1622float2(*reinterpret_cast<__nv_bfloat162*>(&kr.y));
    float2 f2 = __bfloat1622float2(*reinterpret_cast<__nv_bfloat162*>(&kr.z));
    float2 f3 = __bfloat1622float2(*reinterpret_cast<__nv_bfloat162*>(&kr.w));
    f[0] = f0.x; f[1] = f0.y; f[2] = f1.x; f[3] = f1.y;
    f[4] = f2.x; f[5] = f2.y; f[6] = f3.x; f[7] = f3.y;
}

__device__ __forceinline__ float dot8(uint4 kr, const float* vj)
{
    float kf[8];
    unpack8(kr, kf);
    float acc = 0.f;
#pragma unroll
    for (int x = 0; x < 8; ++x) acc = fmaf(kf[x], vj[x], acc);
    return acc;
}

__device__ __forceinline__ float blk_sum(float val, float* red)
{
#pragma unroll
    for (int o = 16; o; o >>= 1) val += __shfl_xor_sync(0xffffffffu, val, o);
    if ((threadIdx.x & 31) == 0) red[threadIdx.x >> 5] = val;
    __syncthreads();
    if (threadIdx.x == 0) {
        float s = 0.f;
        for (int i = 0; i < 32; ++i) s += red[i];
        red[32] = s;
    }
    __syncthreads();
    float r = red[32];
    __syncthreads();
    return r;
}

__device__ __forceinline__ float blk_max(float val, float* red)
{
#pragma unroll
    for (int o = 16; o; o >>= 1) val = fmaxf(val, __shfl_xor_sync(0xffffffffu, val, o));
    if ((threadIdx.x & 31) == 0) red[threadIdx.x >> 5] = val;
    __syncthreads();
    if (threadIdx.x == 0) {
        float s = -3.4e38f;
        for (int i = 0; i < 32; ++i) s = fmaxf(s, red[i]);
        red[32] = s;
    }
    __syncthreads();
    float r = red[32];
    __syncthreads();
    return r;
}

// ---------------------------------------------------------------------------
// Fused kernel: 512 CTAs x 1024 threads. Each CTA pools 4 output rows of one
// batch (32 A_full rows), then arrives at the batch counter. The 64th arriver
// (election, no spinning) runs that batch's Sinkhorn + Kuramoto.
// ---------------------------------------------------------------------------
__global__ void __launch_bounds__(1024, 1) fused_kernel(
    const float* __restrict__ A,
    const float* __restrict__ theta_g, const float* __restrict__ gamma_g,
    const float* __restrict__ omega_g, const float* __restrict__ alpha_g,
    const float* __restrict__ logk_g,  float* __restrict__ out)
{
    extern __shared__ char sm[];
    __nv_bfloat16* Ks = reinterpret_cast<__nv_bfloat16*>(sm);
    float* part  = reinterpret_cast<float*>(sm + 131072);
    float* theta = reinterpret_cast<float*>(sm + 147456);
    float* gam   = theta + 256;
    float* p     = gam + 256;
    float* u     = p + 256;
    float* v     = u + 256;
    float* Kv    = v + 256;
    float* red   = reinterpret_cast<float*>(sm + 153600);
    int*   flg   = reinterpret_cast<int*>(sm + 153792);

    const int t    = threadIdx.x;
    const int wid  = t >> 5;
    const int lane = t & 31;
    const int b    = blockIdx.x >> 6;       // batch
    const int loc  = blockIdx.x & 63;

    // ================= phase 1: pooling (4 output rows per CTA) =============
    {
        const int grp = t >> 8;             // 0..3 : which output row
        const int tl  = t & 255;
        const int I   = loc * 4 + grp;      // output row 0..255
        const float* base = A + ((size_t)b * NF_ + (size_t)I * 8) * NF_;

        float4 a0 = make_float4(0.f, 0.f, 0.f, 0.f);
        float4 a1 = make_float4(0.f, 0.f, 0.f, 0.f);
#pragma unroll
        for (int r = 0; r < 8; ++r) {
            const float4* row = reinterpret_cast<const float4*>(base + (size_t)r * NF_);
            float4 f0 = __ldcs(row + tl);
            float4 f1 = __ldcs(row + tl + 256);
            a0.x += f0.x; a0.y += f0.y; a0.z += f0.z; a0.w += f0.w;
            a1.x += f1.x; a1.y += f1.y; a1.z += f1.z; a1.w += f1.w;
        }
        float s0 = (a0.x + a0.y) + (a0.z + a0.w);
        float s1 = (a1.x + a1.y) + (a1.z + a1.w);
        s0 += __shfl_xor_sync(0xffffffffu, s0, 1);
        s1 += __shfl_xor_sync(0xffffffffu, s1, 1);

        float* srow = part + grp * 256;     // reuse part area
        if (!(tl & 1)) {
            srow[(tl >> 1)]       = s0 * (1.0f / 64.0f);
            srow[128 + (tl >> 1)] = s1 * (1.0f / 64.0f);
        }
        __syncthreads();

        float w = fmaxf(srow[tl], 0.0f);    // relu
        float rv = w;
#pragma unroll
        for (int o = 16; o; o >>= 1) rv += __shfl_xor_sync(0xffffffffu, rv, o);
        float* gred = red + grp * 9;
        if ((tl & 31) == 0) gred[tl >> 5] = rv;
        __syncthreads();
        if (tl == 0) {
            float s = 0.f;
#pragma unroll
            for (int i = 0; i < 8; ++i) s += gred[i];
            gred[8] = s;
        }
        __syncthreads();
        float rowsum = gred[8];

        float W = (rowsum > EPSF) ? (w / (rowsum + EPSF)) : (1.0f / N_);
        float x  = W + EPSF;
        float x2 = x * x, x4 = x2 * x2, x8 = x4 * x4;
        g_K[((size_t)b * N_ + I) * N_ + tl] = __float2bfloat16(x8 * x2); // x^10
    }
    __syncthreads();

    // ================= election: 64th arriver of this batch solves ==========
    if (t == 0) {
        __threadfence();                       // release K rows
        flg[0] = atomicAdd(&g_cnt[b], 1);
    }
    __syncthreads();
    if (flg[0] != 63) return;                  // not elected
    if (t == 0) atomicExch(&g_cnt[b], 0);      // reset for next graph replay
    __threadfence();                           // acquire peers' K rows

    // ================= phase 2: load K + inputs, softmax ====================
    {
        const uint4* gk = reinterpret_cast<const uint4*>(g_K + (size_t)b * N_ * N_);
        uint4* sk = reinterpret_cast<uint4*>(Ks);
#pragma unroll
        for (int x = 0; x < 8; ++x) sk[t + 1024 * x] = gk[t + 1024 * x];
    }
    if (t < 256) {
        theta[t] = theta_g[b * N_ + t];
        gam[t]   = gamma_g[b * N_ + t];
    }
    __syncthreads();
    {
        float val = (t < 256) ? gam[t] : -3.4e38f;
        float m = blk_max(val, red);
        float e = (t < 256) ? expf(gam[t] - m) : 0.f;
        float s = blk_sum(e, red);
        if (t < 256) {
            p[t] = e / s;
            u[t] = 1.0f / N_;
            v[t] = 1.0f / N_;
        }
    }
    __syncthreads();

    // ================= Sinkhorn with mid-iteration fixed-point exit =========
    int early = 0;
    for (int it = 0; it < 10; ++it) {
        if (t == 0) { flg[1] = 0; flg[2] = 0; }
        __syncthreads();

        // --- Kv[i] = sum_j K[i][j] v[j];  u[i] = p[i]/(Kv[i]+EPS) ---
        {
            float vj[8];
#pragma unroll
            for (int x = 0; x < 8; ++x) vj[x] = v[lane * 8 + x];
#pragma unroll
            for (int k = 0; k < 8; ++k) {
                int i = wid * 8 + k;
                uint4 kr = reinterpret_cast<const uint4*>(Ks + i * N_)[lane];
                float acc = dot8(kr, vj);
#pragma unroll
                for (int o = 16; o; o >>= 1) acc += __shfl_xor_sync(0xffffffffu, acc, o);
                if (lane == 0) {
                    float uo = u[i];
                    float un = p[i] / (acc + EPSF);
                    Kv[i] = acc;                     // matvec of current v
                    u[i]  = un;
                    if (un != uo) flg[1] = 1;
                }
            }
        }
        __syncthreads();
        // u unchanged (it>=1, so v = g(u_prev)): exact fixed point; v & Kv final.
        if (it > 0 && flg[1] == 0) { early = 1; break; }

        // --- KTu[j] = sum_i K[i][j] u[i];  v[j] = q/(KTu+EPS) ---
        {
            const int g  = t >> 6;               // 0..15 row groups
            const int jj = (t & 63) * 4;         // 4 consecutive columns
            float4 a4 = make_float4(0.f, 0.f, 0.f, 0.f);
#pragma unroll
            for (int k = 0; k < 16; ++k) {
                int i = g * 16 + k;
                uint2 kk = *reinterpret_cast<const uint2*>(Ks + i * N_ + jj);
                float2 f0 = __bfloat1622float2(*reinterpret_cast<__nv_bfloat162*>(&kk.x));
                float2 f1 = __bfloat1622float2(*reinterpret_cast<__nv_bfloat162*>(&kk.y));
                float ui = u[i];
                a4.x = fmaf(f0.x, ui, a4.x);
                a4.y = fmaf(f0.y, ui, a4.y);
                a4.z = fmaf(f1.x, ui, a4.z);
                a4.w = fmaf(f1.y, ui, a4.w);
            }
            *reinterpret_cast<float4*>(part + g * N_ + jj) = a4;
        }
        __syncthreads();
        if (t < 256) {
            float s = 0.f;
#pragma unroll
            for (int g2 = 0; g2 < 16; ++g2) s += part[g2 * N_ + t];
            float vn = (1.0f / N_) / (s + EPSF);
            if (vn != v[t]) flg[2] = 1;
            v[t] = vn;
        }
        __syncthreads();
        // v unchanged: u_{k+1} = f(v_k) = f(v_{k-1}) = u_k -> fixed point.
        if (flg[2] == 0) { early = 1; break; }   // Kv (of v_{k-1}==v_k) still valid
    }

    if (!early) {
        // ran all 10 iters: v was updated after last Kv; recompute Kv(final v)
        float vj[8];
#pragma unroll
        for (int x = 0; x < 8; ++x) vj[x] = v[lane * 8 + x];
#pragma unroll
        for (int k = 0; k < 8; ++k) {
            int i = wid * 8 + k;
            uint4 kr = reinterpret_cast<const uint4*>(Ks + i * N_)[lane];
            float acc = dot8(kr, vj);
#pragma unroll
            for (int o = 16; o; o >>= 1) acc += __shfl_xor_sync(0xffffffffu, acc, o);
            if (lane == 0) Kv[i] = acc;
        }
        __syncthreads();
    }

    // ================= pi normalization + Kuramoto ==========================
    float sv = (t < 256) ? u[t] * Kv[t] : 0.f;
    float S = blk_sum(sv, red);
    float Sinv = 1.0f / (S + EPSF);

    {
        float vj[8], tj[8];
#pragma unroll
        for (int x = 0; x < 8; ++x) {
            vj[x] = v[lane * 8 + x];
            tj[x] = theta[lane * 8 + x];
        }
        const float4* a4p = reinterpret_cast<const float4*>(alpha_g);
#pragma unroll
        for (int k = 0; k < 8; ++k) {
            int i = wid * 8 + k;
            float ti = theta[i];
            uint4 kr = reinterpret_cast<const uint4*>(Ks + i * N_)[lane];
            float kf[8];
            unpack8(kr, kf);
            float4 al0 = __ldg(a4p + i * 64 + lane * 2);
            float4 al1 = __ldg(a4p + i * 64 + lane * 2 + 1);
            float al[8] = {al0.x, al0.y, al0.z, al0.w, al1.x, al1.y, al1.z, al1.w};
            float acc = 0.f;
#pragma unroll
            for (int x = 0; x < 8; ++x) {
                float d = tj[x] - ti - al[x];
                acc = fmaf(kf[x] * vj[x], __sinf(d), acc);
            }
#pragma unroll
            for (int o = 16; o; o >>= 1) acc += __shfl_xor_sync(0xffffffffu, acc, o);
            if (lane == 0) {
                float coup = u[i] * Sinv * acc;            // K_COUP = 1
                float kap  = log1pf(expf(logk_g[i]));      // softplus
                float td   = omega_g[i] + coup + kap * (gam[i] - ti);
                out[b * N_ + i] = ti + td;                 // DT = 1
            }
        }
    }
}

// ---------------------------------------------------------------------------
extern "C" void kernel_launch(void* const* d_in, const int* in_sizes, int n_in,
                              void* d_out, int out_size)
{
    const float* theta = (const float*)d_in[0];
    const float* gamma = (const float*)d_in[1];
    const float* A     = (const float*)d_in[2];
    const float* omega = (const float*)d_in[3];
    const float* alpha = (const float*)d_in[4];
    const float* logk  = (const float*)d_in[5];
    float* out = (float*)d_out;

    cudaFuncSetAttribute(fused_kernel, cudaFuncAttributeMaxDynamicSharedMemorySize, SMEM_B);
    fused_kernel<<<B_ * 64, 1024, SMEM_B>>>(A, theta, gamma, omega, alpha, logk, out);
}

// round 3
// speedup vs baseline: 1.2185x; 1.2185x over previous
#include <cuda_runtime.h>
#include <cuda_bf16.h>
#include <cstdint>

#define EPSF 1e-8f
static constexpr int B_  = 8;
static constexpr int N_  = 256;
static constexpr int NF_ = 2048;

// K matrices (bf16) staged in global (L2-resident between kernels)
__device__ __nv_bfloat16 g_K[B_ * N_ * N_];
__device__ float g_su[B_ * N_];   // u * Sinv
__device__ float g_v [B_ * N_];

// ---------------------------------------------------------------------------
// Kernel 1: block-mean pooling (8x8) -> row-normalize -> K=(W+EPS)^10, bf16.
// Grid: (256, 8), 256 threads.  (identical to R1 baseline: ~20us, DRAM-bound)
// ---------------------------------------------------------------------------
__global__ void __launch_bounds__(256) pool_build_k(const float* __restrict__ A)
{
    const int I = blockIdx.x, b = blockIdx.y;
    const int t = threadIdx.x;
    const float* base = A + ((size_t)b * NF_ + (size_t)I * 8) * NF_;

    float4 a0 = make_float4(0.f, 0.f, 0.f, 0.f);
    float4 a1 = make_float4(0.f, 0.f, 0.f, 0.f);
#pragma unroll
    for (int r = 0; r < 8; ++r) {
        const float4* row = reinterpret_cast<const float4*>(base + (size_t)r * NF_);
        float4 f0 = __ldcs(row + t);
        float4 f1 = __ldcs(row + t + 256);
        a0.x += f0.x; a0.y += f0.y; a0.z += f0.z; a0.w += f0.w;
        a1.x += f1.x; a1.y += f1.y; a1.z += f1.z; a1.w += f1.w;
    }
    float s0 = (a0.x + a0.y) + (a0.z + a0.w);
    float s1 = (a1.x + a1.y) + (a1.z + a1.w);
    s0 += __shfl_xor_sync(0xffffffffu, s0, 1);
    s1 += __shfl_xor_sync(0xffffffffu, s1, 1);

    __shared__ float srow[256];
    __shared__ float red[9];
    if ((t & 1) == 0) {
        srow[(t >> 1)]       = s0 * (1.0f / 64.0f);
        srow[128 + (t >> 1)] = s1 * (1.0f / 64.0f);
    }
    __syncthreads();

    float w = fmaxf(srow[t], 0.0f);
    float rv = w;
#pragma unroll
    for (int o = 16; o; o >>= 1) rv += __shfl_xor_sync(0xffffffffu, rv, o);
    if ((t & 31) == 0) red[t >> 5] = rv;
    __syncthreads();
    if (t == 0) {
        float s = 0.f;
#pragma unroll
        for (int i = 0; i < 8; ++i) s += red[i];
        red[8] = s;
    }
    __syncthreads();
    float rowsum = red[8];

    float W = (rowsum > EPSF) ? (w / (rowsum + EPSF)) : (1.0f / N_);
    float x  = W + EPSF;
    float x2 = x * x, x4 = x2 * x2, x8 = x4 * x4;
    g_K[((size_t)b * N_ + I) * N_ + t] = __float2bfloat16(x8 * x2);  // x^10
}

// ---------------------------------------------------------------------------
// helpers
// ---------------------------------------------------------------------------
__device__ __forceinline__ void unpack8(uint4 kr, float* f)
{
    float2 f0 = __bfloat1622float2(*reinterpret_cast<__nv_bfloat162*>(&kr.x));
    float2 f1 = __bfloat1622float2(*reinterpret_cast<__nv_bfloat162*>(&kr.y));
    float2 f2 = __bfloat1622float2(*reinterpret_cast<__nv_bfloat162*>(&kr.z));
    float2 f3 = __bfloat1622float2(*reinterpret_cast<__nv_bfloat162*>(&kr.w));
    f[0] = f0.x; f[1] = f0.y; f[2] = f1.x; f[3] = f1.y;
    f[4] = f2.x; f[5] = f2.y; f[6] = f3.x; f[7] = f3.y;
}

__device__ __forceinline__ float dot8(uint4 kr, const float* vj)
{
    float kf[8];
    unpack8(kr, kf);
    float acc = 0.f;
#pragma unroll
    for (int x = 0; x < 8; ++x) acc = fmaf(kf[x], vj[x], acc);
    return acc;
}

__device__ __forceinline__ float blk_sum(float val, float* red)
{
#pragma unroll
    for (int o = 16; o; o >>= 1) val += __shfl_xor_sync(0xffffffffu, val, o);
    if ((threadIdx.x & 31) == 0) red[threadIdx.x >> 5] = val;
    __syncthreads();
    if (threadIdx.x < 32) {
        float s = red[threadIdx.x];
#pragma unroll
        for (int o = 16; o; o >>= 1) s += __shfl_xor_sync(0xffffffffu, s, o);
        if (threadIdx.x == 0) red[32] = s;
    }
    __syncthreads();
    float r = red[32];
    __syncthreads();
    return r;
}

__device__ __forceinline__ float blk_max(float val, float* red)
{
#pragma unroll
    for (int o = 16; o; o >>= 1) val = fmaxf(val, __shfl_xor_sync(0xffffffffu, val, o));
    if ((threadIdx.x & 31) == 0) red[threadIdx.x >> 5] = val;
    __syncthreads();
    if (threadIdx.x < 32) {
        float s = red[threadIdx.x];
#pragma unroll
        for (int o = 16; o; o >>= 1) s = fmaxf(s, __shfl_xor_sync(0xffffffffu, s, o));
        if (threadIdx.x == 0) red[32] = s;
    }
    __syncthreads();
    float r = red[32];
    __syncthreads();
    return r;
}

// ---------------------------------------------------------------------------
// Kernel 2: per-batch Sinkhorn ONLY. One CTA per batch, 1024 threads.
// Mid-iteration fixed-point exit => exactly 3 matvecs on this data.
// Outputs: g_su = u/(S+EPS), g_v = v.
// ---------------------------------------------------------------------------
static constexpr int SOLVE_SMEM = 131072 + 16384 + 5 * 1024 + 34 * 4 + 16;

__global__ void __launch_bounds__(1024, 1) solve_kernel(const float* __restrict__ gamma_g)
{
    extern __shared__ char sm[];
    __nv_bfloat16* Ks = reinterpret_cast<__nv_bfloat16*>(sm);         // 131072 B
    float* part = reinterpret_cast<float*>(sm + 131072);              // 16 * 256 f
    float* gam  = reinterpret_cast<float*>(sm + 131072 + 16384);      // 256 f
    float* p    = gam + 256;
    float* u    = p + 256;
    float* v    = u + 256;
    float* Kv   = v + 256;
    float* red  = Kv + 256;                                           // 33 f
    int*   flg  = reinterpret_cast<int*>(red + 34);

    const int b    = blockIdx.x;
    const int t    = threadIdx.x;
    const int wid  = t >> 5;
    const int lane = t & 31;

    {
        const uint4* gk = reinterpret_cast<const uint4*>(g_K + (size_t)b * N_ * N_);
        uint4* sk = reinterpret_cast<uint4*>(Ks);
#pragma unroll
        for (int x = 0; x < 8; ++x) sk[t + 1024 * x] = gk[t + 1024 * x];
    }
    if (t < 256) gam[t] = gamma_g[b * N_ + t];
    __syncthreads();

    // p = softmax(gamma)
    {
        float val = (t < 256) ? gam[t] : -3.4e38f;
        float m = blk_max(val, red);
        float e = (t < 256) ? expf(gam[t] - m) : 0.f;
        float s = blk_sum(e, red);
        if (t < 256) {
            p[t] = e / s;
            u[t] = 1.0f / N_;
            v[t] = 1.0f / N_;
        }
    }
    __syncthreads();

    // Sinkhorn with mid-iteration fixed-point exit
    int early = 0;
    for (int it = 0; it < 10; ++it) {
        if (t == 0) { flg[1] = 0; flg[2] = 0; }
        __syncthreads();

        // Kv[i] = sum_j K[i][j] v[j];  u[i] = p[i]/(Kv[i]+EPS)
        {
            float vj[8];
#pragma unroll
            for (int x = 0; x < 8; ++x) vj[x] = v[lane * 8 + x];
#pragma unroll
            for (int k = 0; k < 8; ++k) {
                int i = wid * 8 + k;
                uint4 kr = reinterpret_cast<const uint4*>(Ks + i * N_)[lane];
                float acc = dot8(kr, vj);
#pragma unroll
                for (int o = 16; o; o >>= 1) acc += __shfl_xor_sync(0xffffffffu, acc, o);
                if (lane == 0) {
                    float uo = u[i];
                    float un = p[i] / (acc + EPSF);
                    Kv[i] = acc;
                    u[i]  = un;
                    if (un != uo) flg[1] = 1;
                }
            }
        }
        __syncthreads();
        // u unchanged (it>=1 so v=g(u_prev)): exact fixed point, v & Kv final.
        if (it > 0 && flg[1] == 0) { early = 1; break; }

        // KTu[j] = sum_i K[i][j] u[i];  v[j] = q/(KTu+EPS)
        {
            const int g  = t >> 6;
            const int jj = (t & 63) * 4;
            float4 a4 = make_float4(0.f, 0.f, 0.f, 0.f);
#pragma unroll
            for (int k = 0; k < 16; ++k) {
                int i = g * 16 + k;
                uint2 kk = *reinterpret_cast<const uint2*>(Ks + i * N_ + jj);
                float2 f0 = __bfloat1622float2(*reinterpret_cast<__nv_bfloat162*>(&kk.x));
                float2 f1 = __bfloat1622float2(*reinterpret_cast<__nv_bfloat162*>(&kk.y));
                float ui = u[i];
                a4.x = fmaf(f0.x, ui, a4.x);
                a4.y = fmaf(f0.y, ui, a4.y);
                a4.z = fmaf(f1.x, ui, a4.z);
                a4.w = fmaf(f1.y, ui, a4.w);
            }
            *reinterpret_cast<float4*>(part + g * N_ + jj) = a4;
        }
        __syncthreads();
        if (t < 256) {
            float s = 0.f;
#pragma unroll
            for (int g2 = 0; g2 < 16; ++g2) s += part[g2 * N_ + t];
            float vn = (1.0f / N_) / (s + EPSF);
            if (vn != v[t]) flg[2] = 1;
            v[t] = vn;
        }
        __syncthreads();
        // v unchanged => fixed point; Kv (of v_{k-1}==v_k) still valid.
        if (flg[2] == 0) { early = 1; break; }
    }

    if (!early) {
        // all 10 iters ran: recompute Kv with final v
        float vj[8];
#pragma unroll
        for (int x = 0; x < 8; ++x) vj[x] = v[lane * 8 + x];
#pragma unroll
        for (int k = 0; k < 8; ++k) {
            int i = wid * 8 + k;
            uint4 kr = reinterpret_cast<const uint4*>(Ks + i * N_)[lane];
            float acc = dot8(kr, vj);
#pragma unroll
            for (int o = 16; o; o >>= 1) acc += __shfl_xor_sync(0xffffffffu, acc, o);
            if (lane == 0) Kv[i] = acc;
        }
        __syncthreads();
    }

    // S = sum_i u_i * Kv_i ;  write u*Sinv and v
    float sv = (t < 256) ? u[t] * Kv[t] : 0.f;
    float S = blk_sum(sv, red);
    float Sinv = 1.0f / (S + EPSF);
    if (t < 256) {
        g_su[b * N_ + t] = u[t] * Sinv;
        g_v [b * N_ + t] = v[t];
    }
}

// ---------------------------------------------------------------------------
// Kernel 3: Kuramoto epilogue, fully parallel.
// Grid (16 chunks, 8 batches) = 128 CTAs, 256 threads.
// Thread layout: 16 rows/CTA, 16 threads/row, 16 cols/thread.
// ---------------------------------------------------------------------------
__global__ void __launch_bounds__(256) kuramoto_kernel(
    const float* __restrict__ theta_g, const float* __restrict__ gamma_g,
    const float* __restrict__ omega_g, const float* __restrict__ alpha_g,
    const float* __restrict__ logk_g,  float* __restrict__ out)
{
    __shared__ float vsh[256];
    __shared__ float tsh[256];

    const int b     = blockIdx.y;
    const int chunk = blockIdx.x;
    const int t     = threadIdx.x;
    const int row   = t >> 4;            // 0..15
    const int sub   = t & 15;            // 0..15
    const int i     = chunk * 16 + row;  // output row
    const int gi    = b * N_ + i;
    const int j0    = sub * 16;

    vsh[t] = g_v[b * N_ + t];
    tsh[t] = theta_g[b * N_ + t];
    __syncthreads();

    // 16 K values (bf16) for cols j0..j0+15
    uint4 k0 = reinterpret_cast<const uint4*>(g_K + (size_t)gi * N_ + j0)[0];
    uint4 k1 = reinterpret_cast<const uint4*>(g_K + (size_t)gi * N_ + j0)[1];
    float kf[16];
    unpack8(k0, kf);
    unpack8(k1, kf + 8);

    const float4* a4 = reinterpret_cast<const float4*>(alpha_g + (size_t)i * N_ + j0);
    float4 al0 = __ldg(a4 + 0);
    float4 al1 = __ldg(a4 + 1);
    float4 al2 = __ldg(a4 + 2);
    float4 al3 = __ldg(a4 + 3);
    float al[16] = {al0.x, al0.y, al0.z, al0.w, al1.x, al1.y, al1.z, al1.w,
                    al2.x, al2.y, al2.z, al2.w, al3.x, al3.y, al3.z, al3.w};

    const float ti = tsh[i];
    float acc = 0.f;
#pragma unroll
    for (int x = 0; x < 16; ++x) {
        float d = tsh[j0 + x] - ti - al[x];
        acc = fmaf(kf[x] * vsh[j0 + x], __sinf(d), acc);
    }
    // reduce over the 16 threads of this row (contiguous lanes)
#pragma unroll
    for (int o = 8; o; o >>= 1) acc += __shfl_xor_sync(0xffffffffu, acc, o);

    if (sub == 0) {
        float coup = g_su[gi] * acc;                  // K_COUP = 1
        float kap  = log1pf(expf(logk_g[i]));         // softplus
        float td   = omega_g[i] + coup + kap * (gamma_g[gi] - ti);
        out[gi] = ti + td;                            // DT = 1
    }
}

// ---------------------------------------------------------------------------
extern "C" void kernel_launch(void* const* d_in, const int* in_sizes, int n_in,
                              void* d_out, int out_size)
{
    const float* theta = (const float*)d_in[0];
    const float* gamma = (const float*)d_in[1];
    const float* A     = (const float*)d_in[2];
    const float* omega = (const float*)d_in[3];
    const float* alpha = (const float*)d_in[4];
    const float* logk  = (const float*)d_in[5];
    float* out = (float*)d_out;

    dim3 g1(256, 8);
    pool_build_k<<<g1, 256>>>(A);

    cudaFuncSetAttribute(solve_kernel, cudaFuncAttributeMaxDynamicSharedMemorySize, SOLVE_SMEM);
    solve_kernel<<<B_, 1024, SOLVE_SMEM>>>(gamma);

    dim3 g3(16, 8);
    kuramoto_kernel<<<g3, 256>>>(theta, gamma, omega, alpha, logk, out);
}